// round 14
// baseline (speedup 1.0000x reference)
#include <cuda_runtime.h>
#include <cstdint>

typedef unsigned long long u64t;

#define T_STEPS 8192
#define DIM     2048
#define R_CTAS  128
#define R_THR   512   // 16 warps
#define LA      16    // GEMM lookahead rows (== ring depth)

// ---------------- scratch (no allocations allowed) ----------------
// h ping-pong: ONE u64 slot per element = {hi32: step tag, lo32: f32 bits}.
// Relaxed STRONG gpu-scope ops only (atomic + coherent). Dataflow (full W2
// coupling) supplies the causal ordering — no fences.
__device__ __align__(16) u64t g_ht[2][DIM];

// ---------------- f32x2 helpers ----------------
__device__ __forceinline__ u64t fma2(u64t a, u64t b, u64t c) {
    u64t d;
    asm("fma.rn.f32x2 %0, %1, %2, %3;" : "=l"(d) : "l"(a), "l"(b), "l"(c));
    return d;
}
__device__ __forceinline__ float sum2(u64t v) {
    float a, b;
    asm("mov.b64 {%0, %1}, %2;" : "=f"(a), "=f"(b) : "l"(v));
    return a + b;
}

// ---- relaxed strong gpu-scope slot accesses ----
__device__ __forceinline__ u64t ldrlx_u64(const u64t* p) {
    u64t r;
    asm volatile("ld.relaxed.gpu.global.u64 %0, [%1];"
                 : "=l"(r) : "l"(p) : "memory");
    return r;
}
__device__ __forceinline__ void strlx_u64(u64t* p, u64t v) {
    asm volatile("st.relaxed.gpu.global.u64 [%0], %1;"
                 :: "l"(p), "l"(v) : "memory");
}

// ---------------- init: seed h0 tag 0, poison other buffer ----------------
__global__ void init_kernel(const float* __restrict__ h0) {
    int i = blockIdx.x * blockDim.x + threadIdx.x;
    if (i < DIM) {
        g_ht[0][i] = (u64t)__float_as_uint(h0[i]);      // tag 0
        g_ht[1][i] = 0xFFFFFFFF00000000ull;             // poison tag
    }
}

// smem layout (floats): W1s[16][2052] | h_s[2048] | xrow[2048]
//                       | part[2][272] | part2[2][272] | ring[LA][16]
#define W1S_STRIDE 2052
#define SM_W1S   0
#define SM_HS    (16 * W1S_STRIDE)
#define SM_XROW  (SM_HS + 2048)
#define SM_PART  (SM_XROW + 2048)
#define SM_PART2 (SM_PART + 2 * 272)
#define SM_RING  (SM_PART2 + 2 * 272)
#define SM_FLOATS (SM_RING + LA * 16)

// ---------------- fused persistent kernel ----------------
// 128 CTAs x 512 thr, 1 CTA/SM. CTA b owns h rows [16b,16b+16) AND the
// matching pre columns. The per-step N-slice GEMM chunk (pre row t+LA)
// runs entirely in the poll-wait shadow; its partials reduce one step
// later on the existing __syncthreads and land in a smem ring.
__global__ void __launch_bounds__(R_THR, 1)
fused_kernel(const float* __restrict__ X,
             const float* __restrict__ W1, const float* __restrict__ b1,
             const float* __restrict__ W2, const float* __restrict__ b2,
             const float* __restrict__ Wf, const float* __restrict__ bf,
             float* __restrict__ out) {
    extern __shared__ float smf[];
    float* W1s   = smf + SM_W1S;
    float* h_s   = smf + SM_HS;
    float* xrow  = smf + SM_XROW;
    float* partA = smf + SM_PART;
    float* part2 = smf + SM_PART2;
    float* ring  = smf + SM_RING;

    const int tid  = threadIdx.x;
    const int w    = tid >> 5;
    const int l    = tid & 31;
    const int rowl = l & 15;
    const int half = l >> 4;
    const int rbase = blockIdx.x * 16;
    const int cbase = w * 128 + half * 64;

    // ---- prologue: W1 slice to smem (padded stride), W2 slice to regs ----
    for (int idx = tid; idx < 16 * 512; idx += R_THR) {
        int r  = idx >> 9;
        int c4 = idx & 511;
        float4 v = *(const float4*)(W1 + (size_t)(rbase + r) * DIM + c4 * 4);
        float* d = W1s + r * W1S_STRIDE + c4 * 4;
        d[0] = v.x; d[1] = v.y; d[2] = v.z; d[3] = v.w;
    }
    u64t wreg[32];
    {
        const ulonglong2* wp =
            (const ulonglong2*)(W2 + (size_t)(rbase + rowl) * DIM + cbase);
#pragma unroll
        for (int i = 0; i < 16; i++) {
            ulonglong2 v = wp[i];
            wreg[2 * i]     = v.x;
            wreg[2 * i + 1] = v.y;
        }
    }
    const float b2r = b2[rbase + w];
    const float b1c = b1[rbase + w];
    __syncthreads();

    // ---- prologue GEMM: pre rows 0..LA-1 into the ring ----
    for (int r = 0; r < LA; r++) {
        float4 xv = *(const float4*)(X + (size_t)r * DIM + w * 128 + l * 4);
        *(float4*)(xrow + w * 128 + l * 4) = xv;
        __syncwarp();
        const ulonglong2* xp  = (const ulonglong2*)(xrow + cbase);
        const ulonglong2* w1p = (const ulonglong2*)(W1s + rowl * W1S_STRIDE + cbase);
        u64t a0 = 0ull, a1 = 0ull;
#pragma unroll
        for (int i = 0; i < 16; i++) {
            ulonglong2 wv = w1p[i];
            ulonglong2 xr = xp[i];
            a0 = fma2(wv.x, xr.x, a0);
            a1 = fma2(wv.y, xr.y, a1);
        }
        float s2 = sum2(a0) + sum2(a1);
        s2 += __shfl_xor_sync(0xffffffffu, s2, 16);
        if (half == 0) part2[w * 17 + rowl] = s2;
        __syncthreads();
        float g = (l < 16) ? part2[l * 17 + w] : 0.f;
        g += __shfl_xor_sync(0xffffffffu, g, 8);
        g += __shfl_xor_sync(0xffffffffu, g, 4);
        g += __shfl_xor_sync(0xffffffffu, g, 2);
        g += __shfl_xor_sync(0xffffffffu, g, 1);
        if (l == 0) ring[(r & (LA - 1)) * 16 + w] = g + b1c;
        __syncthreads();
    }

    // ---- scan ----
    for (int t = 0; t < T_STEPS; t++) {
        const unsigned tg = (unsigned)t;
        const int p = t & 1;
        const bool doG = (t + LA) < T_STEPS;

        float4 xv;
        if (doG)   // future X row; latency hidden under the poll
            xv = *(const float4*)(X + (size_t)(t + LA) * DIM + w * 128 + l * 4);

        // poll own 128 cols: 4 parallel relaxed loads; nanosleep backoff
        {
            const u64t* base = g_ht[p] + w * 128 + l;
            u64t v0, v1, v2, v3;
            for (;;) {
                v0 = ldrlx_u64(base);
                v1 = ldrlx_u64(base + 32);
                v2 = ldrlx_u64(base + 64);
                v3 = ldrlx_u64(base + 96);
                if (((unsigned)(v0 >> 32) == tg) & ((unsigned)(v1 >> 32) == tg) &
                    ((unsigned)(v2 >> 32) == tg) & ((unsigned)(v3 >> 32) == tg))
                    break;
                __nanosleep(50);
            }
            h_s[w * 128 + l]      = __uint_as_float((unsigned)v0);
            h_s[w * 128 + l + 32] = __uint_as_float((unsigned)v1);
            h_s[w * 128 + l + 64] = __uint_as_float((unsigned)v2);
            h_s[w * 128 + l + 96] = __uint_as_float((unsigned)v3);
        }
        if (doG) *(float4*)(xrow + w * 128 + l * 4) = xv;
        __syncwarp();

        // h-dot (critical)
        {
            const ulonglong2* hp = (const ulonglong2*)(h_s + cbase);
            u64t a0 = 0ull, a1 = 0ull;
#pragma unroll
            for (int i = 0; i < 16; i++) {
                ulonglong2 hv = hp[i];
                a0 = fma2(wreg[2 * i],     hv.x, a0);
                a1 = fma2(wreg[2 * i + 1], hv.y, a1);
            }
            float s = sum2(a0) + sum2(a1);
            s += __shfl_xor_sync(0xffffffffu, s, 16);
            if (half == 0) (partA + (t & 1) * 272)[w * 17 + rowl] = s;
        }
        __syncthreads();

        // critical reduce + publish
        {
            const float* pb = partA + (t & 1) * 272;
            float v = (l < 16) ? pb[l * 17 + w] : 0.f;
            v += __shfl_xor_sync(0xffffffffu, v, 8);
            v += __shfl_xor_sync(0xffffffffu, v, 4);
            v += __shfl_xor_sync(0xffffffffu, v, 2);
            v += __shfl_xor_sync(0xffffffffu, v, 1);
            if (l == 0) {
                float prev = ring[(t & (LA - 1)) * 16 + w];   // pre[t][rbase+w]
                float hnew = fmaxf(v + prev + b2r, 0.f);
                u64t pkd = ((u64t)(tg + 1u) << 32) | (u64t)__float_as_uint(hnew);
                strlx_u64(&g_ht[p ^ 1][rbase + w], pkd);
            }
        }

        // shadow: finalize pre row (t-1+LA) from last step's partials
        if (t >= 1 && (t - 1 + LA) < T_STEPS) {
            const float* p2b = part2 + ((t - 1) & 1) * 272;
            float g = (l < 16) ? p2b[l * 17 + w] : 0.f;
            g += __shfl_xor_sync(0xffffffffu, g, 8);
            g += __shfl_xor_sync(0xffffffffu, g, 4);
            g += __shfl_xor_sync(0xffffffffu, g, 2);
            g += __shfl_xor_sync(0xffffffffu, g, 1);
            if (l == 0) ring[((t - 1 + LA) & (LA - 1)) * 16 + w] = g + b1c;
        }

        // shadow: GEMM dot for pre row (t+LA); reduced next step
        if (doG) {
            const ulonglong2* xp  = (const ulonglong2*)(xrow + cbase);
            const ulonglong2* w1p = (const ulonglong2*)(W1s + rowl * W1S_STRIDE + cbase);
            u64t c0 = 0ull, c1 = 0ull;
#pragma unroll
            for (int i = 0; i < 16; i++) {
                ulonglong2 wv = w1p[i];
                ulonglong2 xr = xp[i];
                c0 = fma2(wv.x, xr.x, c0);
                c1 = fma2(wv.y, xr.y, c1);
            }
            float s2 = sum2(c0) + sum2(c1);
            s2 += __shfl_xor_sync(0xffffffffu, s2, 16);
            if (half == 0) (part2 + (t & 1) * 272)[w * 17 + rowl] = s2;
        }
    }

    // ---- fused head: block 0 computes out = h_T @ Wf^T + bf ----
    if (blockIdx.x == 0) {
        {
            const u64t* base = g_ht[0] + w * 128 + l;   // T_STEPS even -> buf 0
            const unsigned tg = (unsigned)T_STEPS;
            u64t v0, v1, v2, v3;
            for (;;) {
                v0 = ldrlx_u64(base);
                v1 = ldrlx_u64(base + 32);
                v2 = ldrlx_u64(base + 64);
                v3 = ldrlx_u64(base + 96);
                if (((unsigned)(v0 >> 32) == tg) & ((unsigned)(v1 >> 32) == tg) &
                    ((unsigned)(v2 >> 32) == tg) & ((unsigned)(v3 >> 32) == tg))
                    break;
                __nanosleep(50);
            }
            h_s[w * 128 + l]      = __uint_as_float((unsigned)v0);
            h_s[w * 128 + l + 32] = __uint_as_float((unsigned)v1);
            h_s[w * 128 + l + 64] = __uint_as_float((unsigned)v2);
            h_s[w * 128 + l + 96] = __uint_as_float((unsigned)v3);
        }
        __syncthreads();
        if (w < 4) {
            float s = 0.f;
            for (int d = l; d < DIM; d += 32)
                s += h_s[d] * Wf[(size_t)w * DIM + d];
            s += __shfl_xor_sync(0xffffffffu, s, 16);
            s += __shfl_xor_sync(0xffffffffu, s, 8);
            s += __shfl_xor_sync(0xffffffffu, s, 4);
            s += __shfl_xor_sync(0xffffffffu, s, 2);
            s += __shfl_xor_sync(0xffffffffu, s, 1);
            if (l == 0) out[w] = s + bf[w];
        }
    }
}

extern "C" void kernel_launch(void* const* d_in, const int* in_sizes, int n_in,
                              void* d_out, int out_size) {
    const float* x  = (const float*)d_in[0];
    const float* h0 = (const float*)d_in[1];
    const float* W1 = (const float*)d_in[2];
    const float* b1 = (const float*)d_in[3];
    const float* W2 = (const float*)d_in[4];
    const float* b2 = (const float*)d_in[5];
    const float* Wf = (const float*)d_in[6];
    const float* bf = (const float*)d_in[7];
    float* out = (float*)d_out;

    const int smem_bytes = SM_FLOATS * (int)sizeof(float);   // ~153 KB
    cudaFuncSetAttribute(fused_kernel,
                         cudaFuncAttributeMaxDynamicSharedMemorySize, smem_bytes);

    init_kernel<<<8, 256>>>(h0);
    fused_kernel<<<R_CTAS, R_THR, smem_bytes>>>(x, W1, b1, W2, b2, Wf, bf, out);
}